// round 6
// baseline (speedup 1.0000x reference)
#include <cuda_runtime.h>
#include <cuda_fp16.h>
#include <cstdint>

#define NN     32768
#define KNB    16
#define FD     128
#define NEG    0.2f
#define NTILES 4096          // 524288 edges / 128

// ---------------- device scratch ----------------
__device__ __align__(16) float g_U[2 * FD * FD];     // U[m][o][f] fp32
__device__ __align__(16) float g_nproj[NN * FD];     // nodes @ W^T + ba (folded)

// ---------------- smem layout for k_main ----------------
#define PB_BYTES  528        // B row pitch bytes: 264 fp16 (256 K + 8 pad)
#define PA_BYTES  144        // A row pitch bytes: 72 fp16 (64 K + 8 pad)
#define SM_B      0
#define SM_A      67584      // 128 * 528
#define A_STAGE   18432      // 128 * 144
#define SMEM_MAIN 104448     // 67584 + 2*18432

// ---------------- helpers ----------------
__device__ __forceinline__ uint32_t smem_u32(const void* p) {
    uint32_t a;
    asm("{ .reg .u64 t; cvta.to.shared.u64 t, %1; cvt.u32.u64 %0, t; }" : "=r"(a) : "l"(p));
    return a;
}

__device__ __forceinline__ uint2 cvt4(float4 x) {
    __half2 a = __floats2half2_rn(x.x, x.y);
    __half2 b = __floats2half2_rn(x.z, x.w);
    uint2 r;
    r.x = *reinterpret_cast<uint32_t*>(&a);
    r.y = *reinterpret_cast<uint32_t*>(&b);
    return r;
}

#define LDSM4(r, addr) \
    asm volatile("ldmatrix.sync.aligned.m8n8.x4.shared.b16 {%0,%1,%2,%3}, [%4];" \
        : "=r"((r)[0]), "=r"((r)[1]), "=r"((r)[2]), "=r"((r)[3]) : "r"(addr))

#define MMA(d, a, b0_, b1_) \
    asm volatile("mma.sync.aligned.m16n8k16.row.col.f32.f16.f16.f32 " \
        "{%0,%1,%2,%3}, {%4,%5,%6,%7}, {%8,%9}, {%0,%1,%2,%3};" \
        : "+f"((d)[0]), "+f"((d)[1]), "+f"((d)[2]), "+f"((d)[3]) \
        : "r"((a)[0]), "r"((a)[1]), "r"((a)[2]), "r"((a)[3]), "r"(b0_), "r"(b1_))

// ---------------------------------------------------------------------------
// k_pre: merged U precompute + node projection.
//   blocks [0,16)   : U[m][o][f] = sum_op Wa[o][m*128+op] * W[op][f]  (16 rows/blk)
//   blocks [16,528) : nproj[n][o] = sum_f nodes[n][f] * W[o][f] + ba[o]
// ---------------------------------------------------------------------------
#define PITCH 132
__device__ __forceinline__ void fma2(unsigned long long &d, unsigned long long a, unsigned long long b) {
    asm("fma.rn.f32x2 %0, %1, %2, %0;" : "+l"(d) : "l"(a), "l"(b));
}
__device__ __forceinline__ float hsum2(unsigned long long v) {
    float lo, hi;
    asm("mov.b64 {%0, %1}, %2;" : "=f"(lo), "=f"(hi) : "l"(v));
    return lo + hi;
}

__global__ __launch_bounds__(256, 2) void k_pre(const float* __restrict__ nodes,
                                                const float* __restrict__ W,
                                                const float* __restrict__ Wa,
                                                const float* __restrict__ ba) {
    extern __shared__ float smf[];
    const int tid = threadIdx.x;

    if (blockIdx.x < 16) {
        // ---- computeU part: rows R0..R0+15 of U-as-[256][128] ----
        float* sW = smf;            // [128][128]
        float* sT = smf + 16384;    // WaT [128 ops][16 rows]
        for (int i = tid; i < 16384; i += 256) sW[i] = __ldg(W + i);
        const int R0 = blockIdx.x * 16;
        for (int idx = tid; idx < 2048; idx += 256) {
            const int r = idx & 15, op = idx >> 4;
            const int R = R0 + r, m = R >> 7, o = R & 127;
            sT[op * 16 + r] = __ldg(Wa + o * 256 + m * 128 + op);
        }
        __syncthreads();
        const int f = tid & 127, rh = tid >> 7;
        float acc[8];
#pragma unroll
        for (int j = 0; j < 8; ++j) acc[j] = 0.f;
#pragma unroll 8
        for (int op = 0; op < 128; ++op) {
            const float w = sW[op * 128 + f];
            float4 wa0 = *reinterpret_cast<const float4*>(sT + op * 16 + rh * 8);
            float4 wa1 = *reinterpret_cast<const float4*>(sT + op * 16 + rh * 8 + 4);
            acc[0] += w * wa0.x; acc[1] += w * wa0.y; acc[2] += w * wa0.z; acc[3] += w * wa0.w;
            acc[4] += w * wa1.x; acc[5] += w * wa1.y; acc[6] += w * wa1.z; acc[7] += w * wa1.w;
        }
#pragma unroll
        for (int j = 0; j < 8; ++j)
            g_U[(R0 + rh * 8 + j) * 128 + f] = acc[j];
        return;
    }

    // ---- nproj part ----
    float* sW = smf;
    float* sRowBase = smf + FD * PITCH;
    for (int i = tid; i < FD * FD; i += 256)
        sW[(i >> 7) * PITCH + (i & 127)] = W[i];
    __syncthreads();
    const int warp = tid >> 5, lane = tid & 31;
    float* sR = sRowBase + warp * 8 * FD;
    const int base = ((blockIdx.x - 16) * 8 + warp) * 8;
#pragma unroll
    for (int r = 0; r < 8; ++r) {
        float4 v = reinterpret_cast<const float4*>(nodes + (size_t)(base + r) * FD)[lane];
        reinterpret_cast<float4*>(sR + r * FD)[lane] = v;
    }
    __syncwarp();
    const ulonglong2* up[4];
#pragma unroll
    for (int j = 0; j < 4; ++j)
        up[j] = reinterpret_cast<const ulonglong2*>(sW + (lane + 32 * j) * PITCH);
    unsigned long long acc[8][4];
#pragma unroll
    for (int r = 0; r < 8; ++r)
#pragma unroll
        for (int j = 0; j < 4; ++j) acc[r][j] = 0ull;
#pragma unroll 4
    for (int k4 = 0; k4 < 32; ++k4) {
        ulonglong2 u[4];
#pragma unroll
        for (int j = 0; j < 4; ++j) u[j] = up[j][k4];
#pragma unroll
        for (int r = 0; r < 8; ++r) {
            ulonglong2 a = reinterpret_cast<const ulonglong2*>(sR + r * FD)[k4];
#pragma unroll
            for (int j = 0; j < 4; ++j) { fma2(acc[r][j], a.x, u[j].x); fma2(acc[r][j], a.y, u[j].y); }
        }
    }
#pragma unroll
    for (int r = 0; r < 8; ++r)
#pragma unroll
        for (int j = 0; j < 4; ++j) {
            const int col = lane + 32 * j;
            g_nproj[(size_t)(base + r) * FD + col] = hsum2(acc[r][j]) + __ldg(ba + col);
        }
}

// ---------------------------------------------------------------------------
// Main: persistent HMMA kernel, single fp16 term, deferred ping-pong epilogue.
// Tile = 128 edges x 128 out, K=256. 16 warps: 4(M) x 4(N), warp tile 32x32.
// Epilogue of tile t-1 interleaved with MMA chunks of tile t.
// ---------------------------------------------------------------------------
__global__ __launch_bounds__(512, 1) void k_main(
    const float* __restrict__ neighbors, const float* __restrict__ aspects,
    const float* __restrict__ att, const float* __restrict__ bias,
    float* __restrict__ out) {

    extern __shared__ __align__(16) char sm[];
    const int tid = threadIdx.x, lane = tid & 31, wid = tid >> 5;
    const int warp_m = wid >> 2, warp_n = wid & 3;
    const int m0 = warp_m * 32, n0 = warp_n * 32;
    const uint32_t smBase = smem_u32(sm);

    // ---- build resident B = fp16(U1|U2), K-major row per output col ----
    for (int idx = tid; idx < 8192; idx += 512) {
        float4 x = __ldg(reinterpret_cast<const float4*>(g_U) + idx);
        uint2 h = cvt4(x);
        const int f4 = idx & 31, o = (idx >> 5) & 127, m = idx >> 12;
        const int off = o * PB_BYTES + (m * 128 + f4 * 4) * 2;
        *reinterpret_cast<uint2*>(sm + SM_B + off) = h;
    }
    __syncthreads();

    const int q = lane & 3, r = lane >> 2;

    float acc[2][2][4][4];   // [set][mt][nt][frag]
#pragma unroll
    for (int s = 0; s < 2; ++s)
#pragma unroll
        for (int mt = 0; mt < 2; ++mt)
#pragma unroll
            for (int nt = 0; nt < 4; ++nt)
#pragma unroll
                for (int i = 0; i < 4; ++i) acc[s][mt][nt][i] = 0.f;

    // ldmatrix lane base offsets
    const int lane15 = lane & 15, laneHi = lane >> 4;
    const uint32_t aRowOff = (uint32_t)((m0 + lane15) * PA_BYTES + laneHi * 16);
    const uint32_t aSt[2] = { smBase + SM_A + aRowOff, smBase + SM_A + A_STAGE + aRowOff };
    const uint32_t bRow   = smBase + SM_B + (n0 + lane15) * PB_BYTES + laneHi * 16;

    const int grid = gridDim.x;
    const int firstTile = blockIdx.x;
    float4 raw[4];
    int tile = firstTile;
    if (tile < NTILES) {   // prologue: chunk 0 of first tile
        const float* src = neighbors + (size_t)tile * 16384 + (tid >> 4) * 128 + (tid & 15) * 4;
#pragma unroll
        for (int j = 0; j < 4; ++j)
            raw[j] = __ldg(reinterpret_cast<const float4*>(src + j * 4096));
    }

    int set = 0;

    // epilogue piece: process (mt=c>>1, nt in {(c&1)*2, +1}) of acc[set^1] for tile pt
#define EPI_PIECE(c_) do {                                                        \
        const int mt_ = (c_) >> 1;                                                \
        const int pt_ = tile - grid;                                              \
        const int edge0 = pt_ * 128 + m0 + mt_ * 16;                              \
        const float attA = __ldg(att + edge0 + r);                                \
        const float attB = __ldg(att + edge0 + 8 + r);                            \
        const int node = edge0 >> 4;                                              \
        const float* np = g_nproj + (size_t)node * FD;                            \
        _Pragma("unroll")                                                         \
        for (int k_ = 0; k_ < 2; ++k_) {                                          \
            const int nt_ = ((c_) & 1) * 2 + k_;                                  \
            const int col0 = n0 + nt_ * 8 + q * 2;                                \
            const float nb0 = __ldg(np + col0);                                   \
            const float nb1 = __ldg(np + col0 + 1);                               \
            float* a4 = acc[set ^ 1][mt_][nt_];                                   \
            float v0 = a4[0] + nb0, v1 = a4[1] + nb1;                             \
            float v2 = a4[2] + nb0, v3 = a4[3] + nb1;                             \
            v0 = fmaxf(v0, 0.f) + NEG * fminf(v0, 0.f);                           \
            v1 = fmaxf(v1, 0.f) + NEG * fminf(v1, 0.f);                           \
            v2 = fmaxf(v2, 0.f) + NEG * fminf(v2, 0.f);                           \
            v3 = fmaxf(v3, 0.f) + NEG * fminf(v3, 0.f);                           \
            float s0 = attA * __expf(v0) + attB * __expf(v2);                     \
            float s1 = attA * __expf(v1) + attB * __expf(v3);                     \
            s0 += __shfl_xor_sync(0xFFFFFFFFu, s0, 4);                            \
            s1 += __shfl_xor_sync(0xFFFFFFFFu, s1, 4);                            \
            s0 += __shfl_xor_sync(0xFFFFFFFFu, s0, 8);                            \
            s1 += __shfl_xor_sync(0xFFFFFFFFu, s1, 8);                            \
            s0 += __shfl_xor_sync(0xFFFFFFFFu, s0, 16);                           \
            s1 += __shfl_xor_sync(0xFFFFFFFFu, s1, 16);                           \
            if (r == 0) {                                                         \
                float x0 = s0 + __ldg(bias + col0);                               \
                float x1 = s1 + __ldg(bias + col0 + 1);                           \
                float2 o2;                                                        \
                o2.x = (x0 > 0.f) ? x0 : expm1f(x0);                              \
                o2.y = (x1 > 0.f) ? x1 : expm1f(x1);                              \
                *reinterpret_cast<float2*>(out + (size_t)node * FD + col0) = o2;  \
            }                                                                     \
            a4[0] = a4[1] = a4[2] = a4[3] = 0.f;                                  \
        }                                                                         \
    } while (0)

#pragma unroll 1
    for (; tile < NTILES; tile += grid) {
        const bool havePrev = (tile != firstTile);
#pragma unroll
        for (int c = 0; c < 4; ++c) {
            const int stage = c & 1;
            // STS current chunk (fp32 -> fp16)
            {
                char* aP = sm + SM_A + stage * A_STAGE;
                const int mb = tid >> 4, sub = tid & 15;
#pragma unroll
                for (int j = 0; j < 4; ++j) {
                    uint2 h = cvt4(raw[j]);
                    const int row = mb + j * 32;
                    *reinterpret_cast<uint2*>(aP + row * PA_BYTES + sub * 8) = h;
                }
            }
            __syncthreads();
            // prefetch next chunk (or next tile's chunk 0)
            {
                int nc = c + 1, nt_ = tile;
                if (nc == 4) { nc = 0; nt_ = tile + grid; }
                if (nt_ < NTILES) {
                    const float* base = (nc < 2) ? neighbors : aspects;
                    const float* src = base + (size_t)nt_ * 16384 + (nc & 1) * 64
                                     + (tid >> 4) * 128 + (tid & 15) * 4;
#pragma unroll
                    for (int j = 0; j < 4; ++j)
                        raw[j] = __ldg(reinterpret_cast<const float4*>(src + j * 4096));
                }
            }
            // MMA on chunk c into acc[set]
            {
                const uint32_t aBase = aSt[stage];
                const uint32_t bC    = (uint32_t)(c * 128);
#pragma unroll
                for (int ks = 0; ks < 4; ++ks) {
                    const uint32_t ko = ks * 32;
                    uint32_t ah[2][4], bh[2][4];
#pragma unroll
                    for (int mt = 0; mt < 2; ++mt) LDSM4(ah[mt], aBase + mt * (16 * PA_BYTES) + ko);
                    LDSM4(bh[0], bRow + bC + ko);
                    LDSM4(bh[1], bRow + 16 * PB_BYTES + bC + ko);
#pragma unroll
                    for (int mt = 0; mt < 2; ++mt)
#pragma unroll
                        for (int nt = 0; nt < 4; ++nt) {
                            const int g = nt >> 1, s = nt & 1;
                            MMA(acc[set][mt][nt], ah[mt], bh[g][s], bh[g][2 + s]);
                        }
                }
            }
            // deferred epilogue piece for previous tile (overlaps with MMA stream)
            if (havePrev) EPI_PIECE(c);
        }
        set ^= 1;
    }

    // drain: epilogue for the last processed tile (acc[set^1], pt = tile-grid)
    if (tile - grid >= firstTile && firstTile < NTILES) {
#pragma unroll
        for (int c = 0; c < 4; ++c) EPI_PIECE(c);
    }
#undef EPI_PIECE
}

// ---------------------------------------------------------------------------
extern "C" void kernel_launch(void* const* d_in, const int* in_sizes, int n_in,
                              void* d_out, int out_size) {
    const float* nodes     = (const float*)d_in[0];
    const float* neighbors = (const float*)d_in[1];
    const float* aspects   = (const float*)d_in[2];
    const float* att       = (const float*)d_in[3];
    const float* W         = (const float*)d_in[4];
    const float* Wa        = (const float*)d_in[5];
    const float* ba        = (const float*)d_in[6];
    const float* bias      = (const float*)d_in[7];
    float* out = (float*)d_out;

    int dev = 0, nsm = 148;
    cudaGetDevice(&dev);
    cudaDeviceGetAttribute(&nsm, cudaDevAttrMultiProcessorCount, dev);

    const int smem_pre = (FD * PITCH + 8 * 8 * FD) * sizeof(float);      // 100352
    cudaFuncSetAttribute(k_pre,  cudaFuncAttributeMaxDynamicSharedMemorySize, smem_pre);
    cudaFuncSetAttribute(k_main, cudaFuncAttributeMaxDynamicSharedMemorySize, SMEM_MAIN);

    k_pre<<<528, 256, smem_pre>>>(nodes, W, Wa, ba);
    k_main<<<nsm, 512, SMEM_MAIN>>>(neighbors, aspects, att, bias, out);
}

// round 7
// speedup vs baseline: 1.5740x; 1.5740x over previous
#include <cuda_runtime.h>
#include <cuda_fp16.h>
#include <cstdint>

#define NN     32768
#define KNB    16
#define FD     128
#define NEG    0.2f
#define NTILES 8192          // 524288 edges / 64

// ---------------- device scratch ----------------
__device__ __align__(16) float g_U[2 * FD * FD];     // U[m][o][f] fp32
__device__ __align__(16) float g_nproj[NN * FD];     // nodes @ W^T + ba (folded)

// ---------------- smem layout for k_main (per CTA) ----------------
#define PB_BYTES  528        // B row pitch bytes: 264 fp16 (256 K + 8 pad)
#define PA_BYTES  144        // A row pitch bytes: 72 fp16 (64 K + 8 pad)
#define SM_B      0
#define SM_A      67584      // 128 * 528
#define A_STAGE   9216       // 64 * 144
#define SMEM_MAIN 86016      // 67584 + 2*9216

// ---------------- helpers ----------------
__device__ __forceinline__ uint32_t smem_u32(const void* p) {
    uint32_t a;
    asm("{ .reg .u64 t; cvta.to.shared.u64 t, %1; cvt.u32.u64 %0, t; }" : "=r"(a) : "l"(p));
    return a;
}

__device__ __forceinline__ uint2 cvt4(float4 x) {
    __half2 a = __floats2half2_rn(x.x, x.y);
    __half2 b = __floats2half2_rn(x.z, x.w);
    uint2 r;
    r.x = *reinterpret_cast<uint32_t*>(&a);
    r.y = *reinterpret_cast<uint32_t*>(&b);
    return r;
}

#define LDSM4(r, addr) \
    asm volatile("ldmatrix.sync.aligned.m8n8.x4.shared.b16 {%0,%1,%2,%3}, [%4];" \
        : "=r"((r)[0]), "=r"((r)[1]), "=r"((r)[2]), "=r"((r)[3]) : "r"(addr))

#define MMA(d, a, b0_, b1_) \
    asm volatile("mma.sync.aligned.m16n8k16.row.col.f32.f16.f16.f32 " \
        "{%0,%1,%2,%3}, {%4,%5,%6,%7}, {%8,%9}, {%0,%1,%2,%3};" \
        : "+f"((d)[0]), "+f"((d)[1]), "+f"((d)[2]), "+f"((d)[3]) \
        : "r"((a)[0]), "r"((a)[1]), "r"((a)[2]), "r"((a)[3]), "r"(b0_), "r"(b1_))

// ---------------------------------------------------------------------------
// k_pre: merged U precompute + node projection (+ba fold).
//   blocks [0,16)   : U rows
//   blocks [16,528) : nproj
// ---------------------------------------------------------------------------
#define PITCH 132
__device__ __forceinline__ void fma2(unsigned long long &d, unsigned long long a, unsigned long long b) {
    asm("fma.rn.f32x2 %0, %1, %2, %0;" : "+l"(d) : "l"(a), "l"(b));
}
__device__ __forceinline__ float hsum2(unsigned long long v) {
    float lo, hi;
    asm("mov.b64 {%0, %1}, %2;" : "=f"(lo), "=f"(hi) : "l"(v));
    return lo + hi;
}

__global__ __launch_bounds__(256, 2) void k_pre(const float* __restrict__ nodes,
                                                const float* __restrict__ W,
                                                const float* __restrict__ Wa,
                                                const float* __restrict__ ba) {
    extern __shared__ float smf[];
    const int tid = threadIdx.x;

    if (blockIdx.x < 16) {
        float* sW = smf;            // [128][128]
        float* sT = smf + 16384;    // WaT [128 ops][16 rows]
        for (int i = tid; i < 16384; i += 256) sW[i] = __ldg(W + i);
        const int R0 = blockIdx.x * 16;
        for (int idx = tid; idx < 2048; idx += 256) {
            const int r = idx & 15, op = idx >> 4;
            const int R = R0 + r, m = R >> 7, o = R & 127;
            sT[op * 16 + r] = __ldg(Wa + o * 256 + m * 128 + op);
        }
        __syncthreads();
        const int f = tid & 127, rh = tid >> 7;
        float acc[8];
#pragma unroll
        for (int j = 0; j < 8; ++j) acc[j] = 0.f;
#pragma unroll 8
        for (int op = 0; op < 128; ++op) {
            const float w = sW[op * 128 + f];
            float4 wa0 = *reinterpret_cast<const float4*>(sT + op * 16 + rh * 8);
            float4 wa1 = *reinterpret_cast<const float4*>(sT + op * 16 + rh * 8 + 4);
            acc[0] += w * wa0.x; acc[1] += w * wa0.y; acc[2] += w * wa0.z; acc[3] += w * wa0.w;
            acc[4] += w * wa1.x; acc[5] += w * wa1.y; acc[6] += w * wa1.z; acc[7] += w * wa1.w;
        }
#pragma unroll
        for (int j = 0; j < 8; ++j)
            g_U[(R0 + rh * 8 + j) * 128 + f] = acc[j];
        return;
    }

    // ---- nproj part ----
    float* sW = smf;
    float* sRowBase = smf + FD * PITCH;
    for (int i = tid; i < FD * FD; i += 256)
        sW[(i >> 7) * PITCH + (i & 127)] = W[i];
    __syncthreads();
    const int warp = tid >> 5, lane = tid & 31;
    float* sR = sRowBase + warp * 8 * FD;
    const int base = ((blockIdx.x - 16) * 8 + warp) * 8;
#pragma unroll
    for (int r = 0; r < 8; ++r) {
        float4 v = reinterpret_cast<const float4*>(nodes + (size_t)(base + r) * FD)[lane];
        reinterpret_cast<float4*>(sR + r * FD)[lane] = v;
    }
    __syncwarp();
    const ulonglong2* up[4];
#pragma unroll
    for (int j = 0; j < 4; ++j)
        up[j] = reinterpret_cast<const ulonglong2*>(sW + (lane + 32 * j) * PITCH);
    unsigned long long acc[8][4];
#pragma unroll
    for (int r = 0; r < 8; ++r)
#pragma unroll
        for (int j = 0; j < 4; ++j) acc[r][j] = 0ull;
#pragma unroll 4
    for (int k4 = 0; k4 < 32; ++k4) {
        ulonglong2 u[4];
#pragma unroll
        for (int j = 0; j < 4; ++j) u[j] = up[j][k4];
#pragma unroll
        for (int r = 0; r < 8; ++r) {
            ulonglong2 a = reinterpret_cast<const ulonglong2*>(sR + r * FD)[k4];
#pragma unroll
            for (int j = 0; j < 4; ++j) { fma2(acc[r][j], a.x, u[j].x); fma2(acc[r][j], a.y, u[j].y); }
        }
    }
#pragma unroll
    for (int r = 0; r < 8; ++r)
#pragma unroll
        for (int j = 0; j < 4; ++j) {
            const int col = lane + 32 * j;
            g_nproj[(size_t)(base + r) * FD + col] = hsum2(acc[r][j]) + __ldg(ba + col);
        }
}

// ---------------------------------------------------------------------------
// Main: persistent HMMA kernel, fp16, 256 threads, 2 CTAs/SM.
// Tile = 64 edges x 128 out, K=256. 8 warps: 2(M) x 4(N), warp tile 32x32.
// Single barrier per chunk; cross-CTA concurrency hides epilogue.
// ---------------------------------------------------------------------------
__global__ __launch_bounds__(256, 2) void k_main(
    const float* __restrict__ neighbors, const float* __restrict__ aspects,
    const float* __restrict__ att, const float* __restrict__ bias,
    float* __restrict__ out) {

    extern __shared__ __align__(16) char sm[];
    const int tid = threadIdx.x, lane = tid & 31, wid = tid >> 5;
    const int warp_m = wid >> 2, warp_n = wid & 3;
    const int m0 = warp_m * 32, n0 = warp_n * 32;
    const uint32_t smBase = smem_u32(sm);

    // ---- build resident B = fp16(U1|U2), K-major row per output col ----
    for (int idx = tid; idx < 8192; idx += 256) {
        float4 x = __ldg(reinterpret_cast<const float4*>(g_U) + idx);
        uint2 h = cvt4(x);
        const int f4 = idx & 31, o = (idx >> 5) & 127, m = idx >> 12;
        const int off = o * PB_BYTES + (m * 128 + f4 * 4) * 2;
        *reinterpret_cast<uint2*>(sm + SM_B + off) = h;
    }
    __syncthreads();

    const int q = lane & 3, r = lane >> 2;

    float acc[2][4][4];
#pragma unroll
    for (int mt = 0; mt < 2; ++mt)
#pragma unroll
        for (int nt = 0; nt < 4; ++nt)
#pragma unroll
            for (int i = 0; i < 4; ++i) acc[mt][nt][i] = 0.f;

    // ldmatrix lane base offsets
    const int lane15 = lane & 15, laneHi = lane >> 4;
    const uint32_t aRowOff = (uint32_t)((m0 + lane15) * PA_BYTES + laneHi * 16);
    const uint32_t aSt[2] = { smBase + SM_A + aRowOff, smBase + SM_A + A_STAGE + aRowOff };
    const uint32_t bRow   = smBase + SM_B + (n0 + lane15) * PB_BYTES + laneHi * 16;

    const int grid = gridDim.x;
    float4 raw[4];
    int tile = blockIdx.x;
    if (tile < NTILES) {   // prologue: chunk 0 of first tile (64 rows x 64 K)
        const float* src = neighbors + (size_t)tile * 8192 + (tid >> 4) * 128 + (tid & 15) * 4;
#pragma unroll
        for (int j = 0; j < 4; ++j)
            raw[j] = __ldg(reinterpret_cast<const float4*>(src + j * 2048));
    }

#pragma unroll 1
    for (; tile < NTILES; tile += grid) {
#pragma unroll
        for (int c = 0; c < 4; ++c) {
            const int stage = c & 1;
            // STS current chunk (fp32 -> fp16); rows 0..63
            {
                char* aP = sm + SM_A + stage * A_STAGE;
                const int mb = tid >> 4, sub = tid & 15;
#pragma unroll
                for (int j = 0; j < 4; ++j) {
                    uint2 h = cvt4(raw[j]);
                    const int row = mb + j * 16;
                    *reinterpret_cast<uint2*>(aP + row * PA_BYTES + sub * 8) = h;
                }
            }
            __syncthreads();
            // prefetch next chunk (or next tile's chunk 0)
            {
                int nc = c + 1, nt_ = tile;
                if (nc == 4) { nc = 0; nt_ = tile + grid; }
                if (nt_ < NTILES) {
                    const float* base = (nc < 2) ? neighbors : aspects;
                    const float* src = base + (size_t)nt_ * 8192 + (nc & 1) * 64
                                     + (tid >> 4) * 128 + (tid & 15) * 4;
#pragma unroll
                    for (int j = 0; j < 4; ++j)
                        raw[j] = __ldg(reinterpret_cast<const float4*>(src + j * 2048));
                }
            }
            // MMA on chunk c
            {
                const uint32_t aBase = aSt[stage];
                const uint32_t bC    = (uint32_t)(c * 128);
#pragma unroll
                for (int ks = 0; ks < 4; ++ks) {
                    const uint32_t ko = ks * 32;
                    uint32_t ah[2][4], bh[2][4];
#pragma unroll
                    for (int mt = 0; mt < 2; ++mt) LDSM4(ah[mt], aBase + mt * (16 * PA_BYTES) + ko);
                    LDSM4(bh[0], bRow + bC + ko);
                    LDSM4(bh[1], bRow + 16 * PB_BYTES + bC + ko);
#pragma unroll
                    for (int mt = 0; mt < 2; ++mt)
#pragma unroll
                        for (int nt = 0; nt < 4; ++nt) {
                            const int g = nt >> 1, s = nt & 1;
                            MMA(acc[mt][nt], ah[mt], bh[g][s], bh[g][2 + s]);
                        }
                }
            }
            // no trailing barrier: 2-stage ring; next STS targets the stage
            // all warps finished reading before the post-STS sync above.
        }

        // ---- epilogue: leaky->exp->att-weight, reduce 16 edges/node, elu, store ----
#pragma unroll
        for (int mt = 0; mt < 2; ++mt) {
            const int edge0 = tile * 64 + m0 + mt * 16;
            const float attA = __ldg(att + edge0 + r);
            const float attB = __ldg(att + edge0 + 8 + r);
            const int node = edge0 >> 4;
            const float* np = g_nproj + (size_t)node * FD;
#pragma unroll
            for (int nt = 0; nt < 4; ++nt) {
                const int col0 = n0 + nt * 8 + q * 2;
                const float nb0 = __ldg(np + col0);
                const float nb1 = __ldg(np + col0 + 1);
                float* a4 = acc[mt][nt];
                float v0 = a4[0] + nb0, v1 = a4[1] + nb1;
                float v2 = a4[2] + nb0, v3 = a4[3] + nb1;
                v0 = fmaxf(v0, 0.f) + NEG * fminf(v0, 0.f);
                v1 = fmaxf(v1, 0.f) + NEG * fminf(v1, 0.f);
                v2 = fmaxf(v2, 0.f) + NEG * fminf(v2, 0.f);
                v3 = fmaxf(v3, 0.f) + NEG * fminf(v3, 0.f);
                float s0 = attA * __expf(v0) + attB * __expf(v2);
                float s1 = attA * __expf(v1) + attB * __expf(v3);
                s0 += __shfl_xor_sync(0xFFFFFFFFu, s0, 4);
                s1 += __shfl_xor_sync(0xFFFFFFFFu, s1, 4);
                s0 += __shfl_xor_sync(0xFFFFFFFFu, s0, 8);
                s1 += __shfl_xor_sync(0xFFFFFFFFu, s1, 8);
                s0 += __shfl_xor_sync(0xFFFFFFFFu, s0, 16);
                s1 += __shfl_xor_sync(0xFFFFFFFFu, s1, 16);
                if (r == 0) {
                    float x0 = s0 + __ldg(bias + col0);
                    float x1 = s1 + __ldg(bias + col0 + 1);
                    float2 o2;
                    o2.x = (x0 > 0.f) ? x0 : expm1f(x0);
                    o2.y = (x1 > 0.f) ? x1 : expm1f(x1);
                    *reinterpret_cast<float2*>(out + (size_t)node * FD + col0) = o2;
                }
                a4[0] = a4[1] = a4[2] = a4[3] = 0.f;
            }
        }
    }
}

// ---------------------------------------------------------------------------
extern "C" void kernel_launch(void* const* d_in, const int* in_sizes, int n_in,
                              void* d_out, int out_size) {
    const float* nodes     = (const float*)d_in[0];
    const float* neighbors = (const float*)d_in[1];
    const float* aspects   = (const float*)d_in[2];
    const float* att       = (const float*)d_in[3];
    const float* W         = (const float*)d_in[4];
    const float* Wa        = (const float*)d_in[5];
    const float* ba        = (const float*)d_in[6];
    const float* bias      = (const float*)d_in[7];
    float* out = (float*)d_out;

    int dev = 0, nsm = 148;
    cudaGetDevice(&dev);
    cudaDeviceGetAttribute(&nsm, cudaDevAttrMultiProcessorCount, dev);

    const int smem_pre = (FD * PITCH + 8 * 8 * FD) * sizeof(float);      // 100352
    cudaFuncSetAttribute(k_pre,  cudaFuncAttributeMaxDynamicSharedMemorySize, smem_pre);
    cudaFuncSetAttribute(k_main, cudaFuncAttributeMaxDynamicSharedMemorySize, SMEM_MAIN);

    k_pre<<<528, 256, smem_pre>>>(nodes, W, Wa, ba);
    k_main<<<2 * nsm, 256, SMEM_MAIN>>>(neighbors, aspects, att, bias, out);
}

// round 8
// speedup vs baseline: 1.5823x; 1.0052x over previous
#include <cuda_runtime.h>
#include <cuda_fp16.h>
#include <cstdint>

#define NN     32768
#define KNB    16
#define FD     128
#define NEG    0.2f
#define NTILES 4096          // 524288 edges / 128

// ---------------- device scratch ----------------
__device__ __align__(16) float g_U[2 * FD * FD];     // U[m][o][f] fp32
__device__ __align__(16) float g_nproj[NN * FD];     // nodes @ W^T + ba (folded)

// ---------------- smem layout for k_main (per CTA) ----------------
#define PB_BYTES  528        // B row pitch bytes: 264 fp16 (256 K + 8 pad)
#define PA_BYTES  80         // A row pitch bytes: 40 fp16 (32 K + 8 pad)
#define SM_B      0
#define SM_A      67584      // 128 * 528
#define A_STAGE   10240      // 128 * 80
#define SMEM_MAIN 88064      // 67584 + 2*10240

// ---------------- helpers ----------------
__device__ __forceinline__ uint32_t smem_u32(const void* p) {
    uint32_t a;
    asm("{ .reg .u64 t; cvta.to.shared.u64 t, %1; cvt.u32.u64 %0, t; }" : "=r"(a) : "l"(p));
    return a;
}

__device__ __forceinline__ uint2 cvt4(float4 x) {
    __half2 a = __floats2half2_rn(x.x, x.y);
    __half2 b = __floats2half2_rn(x.z, x.w);
    uint2 r;
    r.x = *reinterpret_cast<uint32_t*>(&a);
    r.y = *reinterpret_cast<uint32_t*>(&b);
    return r;
}

#define LDSM4(r, addr) \
    asm volatile("ldmatrix.sync.aligned.m8n8.x4.shared.b16 {%0,%1,%2,%3}, [%4];" \
        : "=r"((r)[0]), "=r"((r)[1]), "=r"((r)[2]), "=r"((r)[3]) : "r"(addr))

#define MMA(d, a, b0_, b1_) \
    asm volatile("mma.sync.aligned.m16n8k16.row.col.f32.f16.f16.f32 " \
        "{%0,%1,%2,%3}, {%4,%5,%6,%7}, {%8,%9}, {%0,%1,%2,%3};" \
        : "+f"((d)[0]), "+f"((d)[1]), "+f"((d)[2]), "+f"((d)[3]) \
        : "r"((a)[0]), "r"((a)[1]), "r"((a)[2]), "r"((a)[3]), "r"(b0_), "r"(b1_))

// ---------------------------------------------------------------------------
// k_preU: U[m][o][f] = sum_op Wa[o][m*128+op] * W[op][f]   (fp32, 16 blocks)
// ---------------------------------------------------------------------------
__global__ __launch_bounds__(256, 2) void k_preU(const float* __restrict__ W,
                                                 const float* __restrict__ Wa) {
    extern __shared__ float smf[];
    const int tid = threadIdx.x;
    float* sW = smf;            // [128][128]
    float* sT = smf + 16384;    // WaT [128 ops][16 rows]
    for (int i = tid; i < 16384; i += 256) sW[i] = __ldg(W + i);
    const int R0 = blockIdx.x * 16;
    for (int idx = tid; idx < 2048; idx += 256) {
        const int r = idx & 15, op = idx >> 4;
        const int R = R0 + r, m = R >> 7, o = R & 127;
        sT[op * 16 + r] = __ldg(Wa + o * 256 + m * 128 + op);
    }
    __syncthreads();
    const int f = tid & 127, rh = tid >> 7;
    float acc[8];
#pragma unroll
    for (int j = 0; j < 8; ++j) acc[j] = 0.f;
#pragma unroll 8
    for (int op = 0; op < 128; ++op) {
        const float w = sW[op * 128 + f];
        float4 wa0 = *reinterpret_cast<const float4*>(sT + op * 16 + rh * 8);
        float4 wa1 = *reinterpret_cast<const float4*>(sT + op * 16 + rh * 8 + 4);
        acc[0] += w * wa0.x; acc[1] += w * wa0.y; acc[2] += w * wa0.z; acc[3] += w * wa0.w;
        acc[4] += w * wa1.x; acc[5] += w * wa1.y; acc[6] += w * wa1.z; acc[7] += w * wa1.w;
    }
#pragma unroll
    for (int j = 0; j < 8; ++j)
        g_U[(R0 + rh * 8 + j) * 128 + f] = acc[j];
}

// ---------------------------------------------------------------------------
// k_nproj_h: nproj = fp16 HMMA of nodes @ W^T + ba. One 128x128 tile / block.
// 8 warps, warp tile 64x32 (2M x 4N), K=128 in one staged pass.
// ---------------------------------------------------------------------------
#define NP_PITCH 272         // 136 fp16 per row (128 K + 8 pad)
#define NP_SMEM  69632       // 2 * 128 * 272

__global__ __launch_bounds__(256, 2) void k_nproj_h(const float* __restrict__ nodes,
                                                    const float* __restrict__ W,
                                                    const float* __restrict__ ba) {
    extern __shared__ __align__(16) char sm[];
    char* sB = sm;                  // W tile, row = out col o
    char* sA = sm + 34816;          // nodes tile
    const int tid = threadIdx.x, lane = tid & 31, wid = tid >> 5;
    const int m0 = (wid >> 2) * 64, n0 = (wid & 3) * 32;
    const uint32_t smBase = smem_u32(sm);
    const int base = blockIdx.x * 128;

    for (int i = tid; i < 4096; i += 256) {       // 4096 float4 = 128x128 fp32
        const int row = i >> 5, c4 = i & 31;
        float4 xb = __ldg(reinterpret_cast<const float4*>(W) + i);
        float4 xa = __ldg(reinterpret_cast<const float4*>(nodes + (size_t)(base + row) * FD) + c4);
        *reinterpret_cast<uint2*>(sB + row * NP_PITCH + c4 * 8) = cvt4(xb);
        *reinterpret_cast<uint2*>(sA + row * NP_PITCH + c4 * 8) = cvt4(xa);
    }
    __syncthreads();

    float acc[4][4][4];
#pragma unroll
    for (int mt = 0; mt < 4; ++mt)
#pragma unroll
        for (int nt = 0; nt < 4; ++nt)
#pragma unroll
            for (int i = 0; i < 4; ++i) acc[mt][nt][i] = 0.f;

    const int lane15 = lane & 15, laneHi = lane >> 4;
    const uint32_t aOff = smBase + 34816 + (m0 + lane15) * NP_PITCH + laneHi * 16;
    const uint32_t bOff = smBase + (n0 + lane15) * NP_PITCH + laneHi * 16;

#pragma unroll
    for (int ks = 0; ks < 8; ++ks) {
        const uint32_t ko = ks * 32;
        uint32_t ah[4][4], bh[2][4];
#pragma unroll
        for (int mt = 0; mt < 4; ++mt) LDSM4(ah[mt], aOff + mt * (16 * NP_PITCH) + ko);
        LDSM4(bh[0], bOff + ko);
        LDSM4(bh[1], bOff + 16 * NP_PITCH + ko);
#pragma unroll
        for (int mt = 0; mt < 4; ++mt)
#pragma unroll
            for (int nt = 0; nt < 4; ++nt) {
                const int g = nt >> 1, s = nt & 1;
                MMA(acc[mt][nt], ah[mt], bh[g][s], bh[g][2 + s]);
            }
    }

    const int q = lane & 3, r = lane >> 2;
#pragma unroll
    for (int mt = 0; mt < 4; ++mt) {
        const int row = base + m0 + mt * 16 + r;
#pragma unroll
        for (int nt = 0; nt < 4; ++nt) {
            const int col0 = n0 + nt * 8 + q * 2;
            const float b0 = __ldg(ba + col0), b1 = __ldg(ba + col0 + 1);
            float* a4 = acc[mt][nt];
            *reinterpret_cast<float2*>(g_nproj + (size_t)row * FD + col0)
                = make_float2(a4[0] + b0, a4[1] + b1);
            *reinterpret_cast<float2*>(g_nproj + (size_t)(row + 8) * FD + col0)
                = make_float2(a4[2] + b0, a4[3] + b1);
        }
    }
}

// ---------------------------------------------------------------------------
// Main: persistent HMMA kernel. Tile = 128 edges x 128 out, K=256.
// 8 warps (2M x 4N), warp tile 64x32. K=32 chunks, 2-stage ring, 2 CTAs/SM.
// ---------------------------------------------------------------------------
__global__ __launch_bounds__(256, 2) void k_main(
    const float* __restrict__ neighbors, const float* __restrict__ aspects,
    const float* __restrict__ att, const float* __restrict__ bias,
    float* __restrict__ out) {

    extern __shared__ __align__(16) char sm[];
    const int tid = threadIdx.x, lane = tid & 31, wid = tid >> 5;
    const int m0 = (wid >> 2) * 64, n0 = (wid & 3) * 32;
    const uint32_t smBase = smem_u32(sm);

    // ---- build resident B = fp16(U1|U2), K-major row per output col ----
    for (int idx = tid; idx < 8192; idx += 256) {
        float4 x = __ldg(reinterpret_cast<const float4*>(g_U) + idx);
        uint2 h = cvt4(x);
        const int f4 = idx & 31, o = (idx >> 5) & 127, m = idx >> 12;
        const int off = o * PB_BYTES + (m * 128 + f4 * 4) * 2;
        *reinterpret_cast<uint2*>(sm + SM_B + off) = h;
    }
    __syncthreads();

    const int q = lane & 3, r = lane >> 2;

    float acc[4][4][4];
#pragma unroll
    for (int mt = 0; mt < 4; ++mt)
#pragma unroll
        for (int nt = 0; nt < 4; ++nt)
#pragma unroll
            for (int i = 0; i < 4; ++i) acc[mt][nt][i] = 0.f;

    const int lane15 = lane & 15, laneHi = lane >> 4;
    const uint32_t aRowOff = (uint32_t)((m0 + lane15) * PA_BYTES + laneHi * 16);
    const uint32_t aSt[2] = { smBase + SM_A + aRowOff, smBase + SM_A + A_STAGE + aRowOff };
    const uint32_t bRow   = smBase + SM_B + (n0 + lane15) * PB_BYTES + laneHi * 16;

    const int grid = gridDim.x;
    const int rb = tid >> 3, sub = tid & 7;      // loader: 32 rows/wave, 8 float4 cols
    float4 raw[4];
    int tile = blockIdx.x;
    if (tile < NTILES) {   // prologue: chunk 0 (neighbors, K cols 0..31)
        const float* src = neighbors + (size_t)tile * 16384 + rb * 128 + sub * 4;
#pragma unroll
        for (int j = 0; j < 4; ++j)
            raw[j] = __ldg(reinterpret_cast<const float4*>(src + j * 4096));
    }

#pragma unroll 1
    for (; tile < NTILES; tile += grid) {
#pragma unroll
        for (int c = 0; c < 8; ++c) {
            const int stage = c & 1;
            // STS current chunk (fp32 -> fp16), 128 rows x 32 K
            {
                char* aP = sm + SM_A + stage * A_STAGE;
#pragma unroll
                for (int j = 0; j < 4; ++j) {
                    const int row = rb + j * 32;
                    *reinterpret_cast<uint2*>(aP + row * PA_BYTES + sub * 8) = cvt4(raw[j]);
                }
            }
            __syncthreads();
            // prefetch next chunk (or next tile's chunk 0)
            {
                int nc = c + 1, nt_ = tile;
                if (nc == 8) { nc = 0; nt_ = tile + grid; }
                if (nt_ < NTILES) {
                    const float* basep = (nc < 4) ? neighbors : aspects;
                    const float* src = basep + (size_t)nt_ * 16384 + (nc & 3) * 32
                                     + rb * 128 + sub * 4;
#pragma unroll
                    for (int j = 0; j < 4; ++j)
                        raw[j] = __ldg(reinterpret_cast<const float4*>(src + j * 4096));
                }
            }
            // MMA on chunk c: 2 k-steps x (6 LDSM + 16 MMA)
            {
                const uint32_t aBase = aSt[stage];
                const uint32_t bC    = (uint32_t)(c * 64);   // K byte offset in B rows
#pragma unroll
                for (int ks = 0; ks < 2; ++ks) {
                    const uint32_t ko = ks * 32;
                    uint32_t ah[4][4], bh[2][4];
#pragma unroll
                    for (int mt = 0; mt < 4; ++mt) LDSM4(ah[mt], aBase + mt * (16 * PA_BYTES) + ko);
                    LDSM4(bh[0], bRow + bC + ko);
                    LDSM4(bh[1], bRow + 16 * PB_BYTES + bC + ko);
#pragma unroll
                    for (int mt = 0; mt < 4; ++mt)
#pragma unroll
                        for (int nt = 0; nt < 4; ++nt) {
                            const int g = nt >> 1, s = nt & 1;
                            MMA(acc[mt][nt], ah[mt], bh[g][s], bh[g][2 + s]);
                        }
                }
            }
        }

        // ---- epilogue: leaky->exp->att-weight, reduce 16 edges/node, elu, store ----
#pragma unroll
        for (int mt = 0; mt < 4; ++mt) {
            const int edge0 = tile * 128 + m0 + mt * 16;
            const float attA = __ldg(att + edge0 + r);
            const float attB = __ldg(att + edge0 + 8 + r);
            const int node = edge0 >> 4;
            const float* np = g_nproj + (size_t)node * FD;
#pragma unroll
            for (int nt = 0; nt < 4; ++nt) {
                const int col0 = n0 + nt * 8 + q * 2;
                const float nb0 = __ldg(np + col0);
                const float nb1 = __ldg(np + col0 + 1);
                float* a4 = acc[mt][nt];
                float v0 = a4[0] + nb0, v1 = a4[1] + nb1;
                float v2 = a4[2] + nb0, v3 = a4[3] + nb1;
                v0 = fmaxf(v0, 0.f) + NEG * fminf(v0, 0.f);
                v1 = fmaxf(v1, 0.f) + NEG * fminf(v1, 0.f);
                v2 = fmaxf(v2, 0.f) + NEG * fminf(v2, 0.f);
                v3 = fmaxf(v3, 0.f) + NEG * fminf(v3, 0.f);
                float s0 = attA * __expf(v0) + attB * __expf(v2);
                float s1 = attA * __expf(v1) + attB * __expf(v3);
                s0 += __shfl_xor_sync(0xFFFFFFFFu, s0, 4);
                s1 += __shfl_xor_sync(0xFFFFFFFFu, s1, 4);
                s0 += __shfl_xor_sync(0xFFFFFFFFu, s0, 8);
                s1 += __shfl_xor_sync(0xFFFFFFFFu, s1, 8);
                s0 += __shfl_xor_sync(0xFFFFFFFFu, s0, 16);
                s1 += __shfl_xor_sync(0xFFFFFFFFu, s1, 16);
                if (r == 0) {
                    float x0 = s0 + __ldg(bias + col0);
                    float x1 = s1 + __ldg(bias + col0 + 1);
                    float2 o2;
                    o2.x = (x0 > 0.f) ? x0 : expm1f(x0);
                    o2.y = (x1 > 0.f) ? x1 : expm1f(x1);
                    *reinterpret_cast<float2*>(out + (size_t)node * FD + col0) = o2;
                }
                a4[0] = a4[1] = a4[2] = a4[3] = 0.f;
            }
        }
    }
}

// ---------------------------------------------------------------------------
extern "C" void kernel_launch(void* const* d_in, const int* in_sizes, int n_in,
                              void* d_out, int out_size) {
    const float* nodes     = (const float*)d_in[0];
    const float* neighbors = (const float*)d_in[1];
    const float* aspects   = (const float*)d_in[2];
    const float* att       = (const float*)d_in[3];
    const float* W         = (const float*)d_in[4];
    const float* Wa        = (const float*)d_in[5];
    const float* ba        = (const float*)d_in[6];
    const float* bias      = (const float*)d_in[7];
    float* out = (float*)d_out;

    int dev = 0, nsm = 148;
    cudaGetDevice(&dev);
    cudaDeviceGetAttribute(&nsm, cudaDevAttrMultiProcessorCount, dev);

    const int smem_preU = (16384 + 2048) * sizeof(float);   // 73728
    cudaFuncSetAttribute(k_preU,    cudaFuncAttributeMaxDynamicSharedMemorySize, smem_preU);
    cudaFuncSetAttribute(k_nproj_h, cudaFuncAttributeMaxDynamicSharedMemorySize, NP_SMEM);
    cudaFuncSetAttribute(k_main,    cudaFuncAttributeMaxDynamicSharedMemorySize, SMEM_MAIN);

    k_preU<<<16, 256, smem_preU>>>(W, Wa);
    k_nproj_h<<<256, 256, NP_SMEM>>>(nodes, W, ba);
    k_main<<<2 * nsm, 256, SMEM_MAIN>>>(neighbors, aspects, att, bias, out);
}